// round 17
// baseline (speedup 1.0000x reference)
#include <cuda_runtime.h>
#include <cstdint>

#define N_NODES 50000
#define IN_FEAT 512
#define OUT_FEAT 256
#define N_EDGES 1600000
#define ALPHA 0.2f

// Scratch (allocation-free rule: __device__ globals).
__device__ float4 g_w_src4[IN_FEAT / 4];
__device__ float4 g_w_tgt4[IN_FEAT / 4];
__device__ float g_s_src[N_NODES];
__device__ float g_s_tgt[N_NODES];

// Monotonic-ticket grid barrier (no reset; safe across graph replays).
__device__ unsigned g_bar = 0;

__device__ __forceinline__ float dot4(float4 a, float4 b) {
    return a.x * b.x + a.y * b.y + a.z * b.z + a.w * b.w;
}

__device__ __forceinline__ void grid_sync(unsigned nblocks) {
    __syncthreads();
    if (threadIdx.x == 0) {
        __threadfence();
        unsigned ticket = atomicAdd(&g_bar, 1u);
        unsigned target = (ticket / nblocks + 1u) * nblocks;
        while (*(volatile unsigned*)&g_bar < target) { }
        __threadfence();
    }
    __syncthreads();
}

__device__ __forceinline__ void prefetch_l2(const void* p) {
    asm volatile("prefetch.global.L2 [%0];" :: "l"(p));
}

// ---------------------------------------------------------------------------
// Kernel 1: phase A (w = W @ a) -> grid barrier -> phase B (node scores).
// Bodies FROZEN from the R13 35.3us version; only addition is a register-free
// L2 prefetch of each warp's first h segment issued before the barrier.
// ---------------------------------------------------------------------------
__global__ __launch_bounds__(256) void ab_kernel(
    const float* __restrict__ h,
    const float* __restrict__ W,
    const float* __restrict__ attn_w,
    int nblocks)
{
    __shared__ float4 sh_ws[IN_FEAT / 4];
    __shared__ float4 sh_wt[IN_FEAT / 4];

    const int tid  = threadIdx.x;
    const int lane = tid & 31;
    const int wid  = tid >> 5;
    const int gw   = blockIdx.x * 8 + wid;
    const int nwarps = nblocks * 8;

    // ---------------- Phase A ----------------------------------------------
    if (gw < IN_FEAT) {
        const float4* wrow4 = reinterpret_cast<const float4*>(W + (size_t)gw * OUT_FEAT);
        const float4* as4   = reinterpret_cast<const float4*>(attn_w);
        const float4* at4   = reinterpret_cast<const float4*>(attn_w + OUT_FEAT);

        float4 w0 = wrow4[lane];
        float4 w1 = wrow4[32 + lane];
        float acc_s = dot4(w0, as4[lane]) + dot4(w1, as4[32 + lane]);
        float acc_t = dot4(w0, at4[lane]) + dot4(w1, at4[32 + lane]);
#pragma unroll
        for (int off = 16; off > 0; off >>= 1) {
            acc_s += __shfl_xor_sync(0xffffffffu, acc_s, off);
            acc_t += __shfl_xor_sync(0xffffffffu, acc_t, off);
        }
        if (lane == 0) {
            reinterpret_cast<float*>(g_w_src4)[gw] = acc_s;
            reinterpret_cast<float*>(g_w_tgt4)[gw] = acc_t;
        }
    }

    // Warm L2 with this warp's first B node while waiting for phase A.
    // Register-free (address-only), outside the B loop: codegen of the
    // frozen B body is unaffected.
    if (gw < N_NODES) {
        const float4* h4p = reinterpret_cast<const float4*>(h + (size_t)gw * IN_FEAT);
        prefetch_l2(h4p + lane);
        prefetch_l2(h4p + 32 + lane);
        prefetch_l2(h4p + 64 + lane);
        prefetch_l2(h4p + 96 + lane);
    }

    grid_sync(nblocks);

    // Stage w vectors into shared (4 KB)
    for (int i = tid; i < IN_FEAT / 4; i += 256) {
        sh_ws[i] = g_w_src4[i];
        sh_wt[i] = g_w_tgt4[i];
    }
    __syncthreads();

    // ---------------- Phase B: warp per node, grid-stride (FROZEN) ---------
    for (int node = gw; node < N_NODES; node += nwarps) {
        const float4* h4 = reinterpret_cast<const float4*>(h + (size_t)node * IN_FEAT);

        float4 hv0 = h4[lane];
        float4 hv1 = h4[32 + lane];
        float4 hv2 = h4[64 + lane];
        float4 hv3 = h4[96 + lane];

        float acc_s = dot4(hv0, sh_ws[lane])      + dot4(hv1, sh_ws[32 + lane]) +
                      dot4(hv2, sh_ws[64 + lane]) + dot4(hv3, sh_ws[96 + lane]);
        float acc_t = dot4(hv0, sh_wt[lane])      + dot4(hv1, sh_wt[32 + lane]) +
                      dot4(hv2, sh_wt[64 + lane]) + dot4(hv3, sh_wt[96 + lane]);

        // Split-half reduction: lo 16 lanes reduce s, hi 16 reduce t.
        float os = __shfl_xor_sync(0xffffffffu, acc_s, 16);
        float ot = __shfl_xor_sync(0xffffffffu, acc_t, 16);
        float v = (lane < 16) ? (acc_s + os) : (acc_t + ot);
#pragma unroll
        for (int off = 8; off > 0; off >>= 1)
            v += __shfl_xor_sync(0xffffffffu, v, off);
        if (lane == 0)  g_s_src[node] = v;
        if (lane == 16) g_s_tgt[node] = v;
    }
}

// ---------------------------------------------------------------------------
// Kernel 2: phase C. R13's proven configuration: exact-fit 1563 blocks,
// 1 int4-group (8 gathers) per thread. Only change: fmaxf leaky-relu.
// ---------------------------------------------------------------------------
__global__ __launch_bounds__(256) void edge_kernel(
    const int* __restrict__ edge_list,
    float*     __restrict__ out)
{
    const int k4 = blockIdx.x * 256 + threadIdx.x;
    if (k4 >= N_EDGES / 4) return;

    int4 s = reinterpret_cast<const int4*>(edge_list)[k4];
    int4 t = reinterpret_cast<const int4*>(edge_list + N_EDGES)[k4];

    float e0 = __ldg(&g_s_src[s.x]) + __ldg(&g_s_tgt[t.x]);
    float e1 = __ldg(&g_s_src[s.y]) + __ldg(&g_s_tgt[t.y]);
    float e2 = __ldg(&g_s_src[s.z]) + __ldg(&g_s_tgt[t.z]);
    float e3 = __ldg(&g_s_src[s.w]) + __ldg(&g_s_tgt[t.w]);

    float4 r;
    r.x = fmaxf(e0, ALPHA * e0);   // leaky_relu: max(e, 0.2e) valid both signs
    r.y = fmaxf(e1, ALPHA * e1);
    r.z = fmaxf(e2, ALPHA * e2);
    r.w = fmaxf(e3, ALPHA * e3);
    reinterpret_cast<float4*>(out)[k4] = r;
}

// ---------------------------------------------------------------------------
extern "C" void kernel_launch(void* const* d_in, const int* in_sizes, int n_in,
                              void* d_out, int out_size) {
    const float* h         = (const float*)d_in[0];
    const int*   edge_list = (const int*)d_in[1];
    const float* W         = (const float*)d_in[2];
    const float* attn_w    = (const float*)d_in[3];
    float* out = (float*)d_out;

    int dev = 0;
    cudaGetDevice(&dev);
    int sms = 148;
    cudaDeviceGetAttribute(&sms, cudaDevAttrMultiProcessorCount, dev);
    int occ = 1;
    cudaOccupancyMaxActiveBlocksPerMultiprocessor(&occ, ab_kernel, 256, 0);
    if (occ < 1) occ = 1;
    int nblocks_ab = sms * occ;            // exactly one co-resident wave
    if (nblocks_ab < 64) nblocks_ab = 64;  // phase A needs >= 512 warps

    ab_kernel<<<nblocks_ab, 256>>>(h, W, attn_w, nblocks_ab);

    // C: exact fit, 1563 blocks (R13 configuration)
    edge_kernel<<<(N_EDGES / 4 + 255) / 256, 256>>>(edge_list, out);
}